// round 1
// baseline (speedup 1.0000x reference)
#include <cuda_runtime.h>
#include <cstdint>
#include <cstddef>

#define BATCH 32
#define SEQ   2048
#define DIM   128
#define QT    64
#define KT    64
#define NT    256
#define P_STRIDE 68

static constexpr int SMEM_FLOATS = QT*DIM + KT*DIM + QT*P_STRIDE;
static constexpr int SMEM_BYTES  = SMEM_FLOATS * 4;

// ---------------------------------------------------------------------------
// JAX threefry-2x32, key = (0, 42)  [jax.random.key(42)]
// Partitionable mode (default in modern JAX): element i gets
//   bits = out0 ^ out1 of threefry2x32(key, (hi32(i), lo32(i))) ; hi32(i)==0 here.
// uniform = bitcast((bits>>9)|0x3f800000) - 1.0 ;  keep = uniform < 0.9f
// ---------------------------------------------------------------------------
__device__ __forceinline__ uint32_t threefry_bits(uint32_t idx)
{
    uint32_t x0 = 0u;              // += ks[0] == 0
    uint32_t x1 = idx + 42u;       // += ks[1] == 42
    const uint32_t ks1 = 42u;
    const uint32_t ks2 = 0x1BD11BDAu ^ 42u;

#define TF_R4(a,b,c,d)                                          \
    x0 += x1; x1 = __funnelshift_l(x1, x1, (a)); x1 ^= x0;      \
    x0 += x1; x1 = __funnelshift_l(x1, x1, (b)); x1 ^= x0;      \
    x0 += x1; x1 = __funnelshift_l(x1, x1, (c)); x1 ^= x0;      \
    x0 += x1; x1 = __funnelshift_l(x1, x1, (d)); x1 ^= x0;

    TF_R4(13,15,26, 6)  x0 += ks1;            x1 += ks2 + 1u;
    TF_R4(17,29,16,24)  x0 += ks2;            x1 += 2u;          // ks0+2
    TF_R4(13,15,26, 6)  /* x0 += ks0(=0) */   x1 += ks1 + 3u;
    TF_R4(17,29,16,24)  x0 += ks1;            x1 += ks2 + 4u;
    TF_R4(13,15,26, 6)  x0 += ks2;            x1 += 5u;          // ks0+5
#undef TF_R4
    return x0 ^ x1;   // partitionable 32-bit fold
}

// ---------------------------------------------------------------------------
// Flash-attention fp32: one CTA = (batch b, 64 q rows). K tile streamed.
// v == k (x2), so the swizzled K tile doubles as the V tile.
// Thread map (tid = ty*16+tx):
//   S stage : rows 4*ty..+3, cols {tx, tx+16, tx+32, tx+48}
//   PV stage: rows 4*ty..+3, d-cols 8*tx..+7
// k_s float4 slots XOR-swizzled: logical d4 stored at slot d4 ^ (c&7).
// ---------------------------------------------------------------------------
__global__ void __launch_bounds__(NT, 2)
attn_kernel(const float* __restrict__ x1, const float* __restrict__ x2,
            float* __restrict__ out)
{
    extern __shared__ float sm[];
    float* q_s = sm;                       // [QT][DIM]
    float* k_s = sm + QT*DIM;              // [KT][DIM] (swizzled)
    float* p_s = sm + QT*DIM + KT*DIM;     // [QT][P_STRIDE]

    const int b   = blockIdx.y;
    const int qt0 = blockIdx.x * QT;
    const int tid = threadIdx.x;
    const int ty  = tid >> 4;
    const int tx  = tid & 15;

    const float* Qg = x1 + ((size_t)(b*SEQ + qt0)) * DIM;
    const float* Kg = x2 + ((size_t)(b*SEQ)) * DIM;

    for (int i = tid; i < QT*DIM/4; i += NT)
        ((float4*)q_s)[i] = ((const float4*)Qg)[i];

    float m[4], l[4], acc[4][8];
#pragma unroll
    for (int i = 0; i < 4; ++i) {
        m[i] = -1e30f; l[i] = 0.0f;
#pragma unroll
        for (int j = 0; j < 8; ++j) acc[i][j] = 0.0f;
    }

    const float SCALE = 3.36358566f;   // 128 ** 0.25 (fp32)

    for (int kt0 = 0; kt0 < SEQ; kt0 += KT) {
        __syncthreads();   // previous PV done before overwriting k_s
#pragma unroll
        for (int idx = tid; idx < KT*DIM/4; idx += NT) {
            const int c  = idx >> 5;          // row within K tile
            const int d4 = idx & 31;          // float4 column
            float4 t = ((const float4*)(Kg + (size_t)(kt0 + c) * DIM))[d4];
            ((float4*)k_s)[(c << 5) | (d4 ^ (c & 7))] = t;
        }
        __syncthreads();

        // ---- S = Q K^T (64x64 tile), fp32 ----
        float s[4][4];
#pragma unroll
        for (int i = 0; i < 4; ++i)
#pragma unroll
            for (int j = 0; j < 4; ++j) s[i][j] = 0.0f;

#pragma unroll
        for (int d0 = 0; d0 < DIM; d0 += 4) {
            const int d4 = d0 >> 2;
            float4 qv[4], kv[4];
#pragma unroll
            for (int i = 0; i < 4; ++i)
                qv[i] = *(const float4*)&q_s[((ty<<2)+i)*DIM + d0];
#pragma unroll
            for (int jj = 0; jj < 4; ++jj) {
                const int c = tx + (jj << 4);
                kv[jj] = ((const float4*)k_s)[(c << 5) | (d4 ^ (tx & 7))];
            }
#pragma unroll
            for (int i = 0; i < 4; ++i) {
#pragma unroll
                for (int jj = 0; jj < 4; ++jj) {
                    s[i][jj] = fmaf(qv[i].x, kv[jj].x, s[i][jj]);
                    s[i][jj] = fmaf(qv[i].y, kv[jj].y, s[i][jj]);
                    s[i][jj] = fmaf(qv[i].z, kv[jj].z, s[i][jj]);
                    s[i][jj] = fmaf(qv[i].w, kv[jj].w, s[i][jj]);
                }
            }
        }

        // ---- online softmax + threefry dropout; P~ tile -> smem ----
#pragma unroll
        for (int i = 0; i < 4; ++i) {
            const int row = (ty << 2) + i;
            float rm = -1e30f;
#pragma unroll
            for (int jj = 0; jj < 4; ++jj) {
                s[i][jj] *= SCALE;
                rm = fmaxf(rm, s[i][jj]);
            }
#pragma unroll
            for (int off = 8; off > 0; off >>= 1)   // reduce across 16-lane row group
                rm = fmaxf(rm, __shfl_xor_sync(0xffffffffu, rm, off));

            const float mnew = fmaxf(m[i], rm);
            const float corr = __expf(m[i] - mnew);
            m[i] = mnew;
            l[i] *= corr;
#pragma unroll
            for (int j = 0; j < 8; ++j) acc[i][j] *= corr;

            const uint32_t base = (uint32_t)(b*SEQ + qt0 + row) * (uint32_t)SEQ
                                + (uint32_t)(kt0 + tx);
            float rsum = 0.0f;
#pragma unroll
            for (int jj = 0; jj < 4; ++jj) {
                const float e = __expf(s[i][jj] - mnew);
                rsum += e;                                    // normalizer: NO dropout
                const uint32_t bits = threefry_bits(base + (jj << 4));
                const float u = __uint_as_float((bits >> 9) | 0x3f800000u) - 1.0f;
                p_s[row*P_STRIDE + tx + (jj << 4)] = (u < 0.9f) ? e : 0.0f;
            }
#pragma unroll
            for (int off = 8; off > 0; off >>= 1)
                rsum += __shfl_xor_sync(0xffffffffu, rsum, off);
            l[i] += rsum;
        }
        __syncthreads();

        // ---- O += P~ V  (V read from swizzled k_s) ----
#pragma unroll
        for (int c0 = 0; c0 < KT; c0 += 4) {
            float4 pv4[4];
#pragma unroll
            for (int i = 0; i < 4; ++i)
                pv4[i] = *(const float4*)&p_s[((ty<<2)+i)*P_STRIDE + c0];
            float pcol[4][4];
#pragma unroll
            for (int i = 0; i < 4; ++i) {
                pcol[i][0] = pv4[i].x; pcol[i][1] = pv4[i].y;
                pcol[i][2] = pv4[i].z; pcol[i][3] = pv4[i].w;
            }
#pragma unroll
            for (int u = 0; u < 4; ++u) {
                const int c  = c0 + u;
                const int sw = c & 7;
                const float4 va = ((const float4*)k_s)[(c << 5) | (((tx<<1)    ) ^ sw)];
                const float4 vb = ((const float4*)k_s)[(c << 5) | (((tx<<1) | 1) ^ sw)];
#pragma unroll
                for (int i = 0; i < 4; ++i) {
                    const float p = pcol[i][u];
                    acc[i][0] = fmaf(p, va.x, acc[i][0]);
                    acc[i][1] = fmaf(p, va.y, acc[i][1]);
                    acc[i][2] = fmaf(p, va.z, acc[i][2]);
                    acc[i][3] = fmaf(p, va.w, acc[i][3]);
                    acc[i][4] = fmaf(p, vb.x, acc[i][4]);
                    acc[i][5] = fmaf(p, vb.y, acc[i][5]);
                    acc[i][6] = fmaf(p, vb.z, acc[i][6]);
                    acc[i][7] = fmaf(p, vb.w, acc[i][7]);
                }
            }
        }
    }

    // ---- epilogue: out = acc / (l * (1-p_drop)) ----
#pragma unroll
    for (int i = 0; i < 4; ++i) {
        const int row = qt0 + (ty << 2) + i;
        const float inv = 1.0f / (l[i] * 0.9f);
        float* op = out + ((size_t)(b*SEQ + row)) * DIM + (tx << 3);
        float4 o1, o2;
        o1.x = acc[i][0]*inv; o1.y = acc[i][1]*inv;
        o1.z = acc[i][2]*inv; o1.w = acc[i][3]*inv;
        o2.x = acc[i][4]*inv; o2.y = acc[i][5]*inv;
        o2.z = acc[i][6]*inv; o2.w = acc[i][7]*inv;
        ((float4*)op)[0] = o1;
        ((float4*)op)[1] = o2;
    }
}

extern "C" void kernel_launch(void* const* d_in, const int* in_sizes, int n_in,
                              void* d_out, int out_size)
{
    (void)in_sizes; (void)n_in; (void)out_size;
    const float* x1 = (const float*)d_in[0];
    const float* x2 = (const float*)d_in[1];
    float* out = (float*)d_out;

    cudaFuncSetAttribute(attn_kernel,
                         cudaFuncAttributeMaxDynamicSharedMemorySize, SMEM_BYTES);

    dim3 grid(SEQ / QT, BATCH);
    attn_kernel<<<grid, NT, SMEM_BYTES>>>(x1, x2, out);
}

// round 2
// speedup vs baseline: 1.0892x; 1.0892x over previous
#include <cuda_runtime.h>
#include <cstdint>
#include <cstddef>

#define BATCH 32
#define SEQ   2048
#define DIM   128
#define QT    128
#define KT    64
#define NT    256
#define PS    68

typedef unsigned long long u64;

static constexpr int SMEM_BYTES = (QT*DIM + KT*DIM + QT*PS) * 4;  // 133120

// ---- packed f32x2 helpers (sm_100a FFMA2 path — ptxas won't auto-fuse) ----
#define FMA2(d, a, b) asm("fma.rn.f32x2 %0, %1, %2, %0;" : "+l"(d) : "l"(a), "l"(b))
#define MUL2IP(d, c)  asm("mul.rn.f32x2 %0, %0, %1;" : "+l"(d) : "l"(c))

__device__ __forceinline__ u64 pack2(float x) {
    u64 r;
    asm("mov.b64 %0, {%1, %1};" : "=l"(r) : "r"(__float_as_uint(x)));
    return r;
}
__device__ __forceinline__ float hadd2(u64 v) {
    uint32_t lo, hi;
    asm("mov.b64 {%0, %1}, %2;" : "=r"(lo), "=r"(hi) : "l"(v));
    return __uint_as_float(lo) + __uint_as_float(hi);
}
__device__ __forceinline__ void unpack2(u64 v, float& a, float& b) {
    uint32_t lo, hi;
    asm("mov.b64 {%0, %1}, %2;" : "=r"(lo), "=r"(hi) : "l"(v));
    a = __uint_as_float(lo); b = __uint_as_float(hi);
}

// ---------------------------------------------------------------------------
// JAX threefry-2x32 (partitionable fold), key = (0, 42). Verified R1.
// ---------------------------------------------------------------------------
__device__ __forceinline__ uint32_t threefry_bits(uint32_t idx)
{
    uint32_t x0 = 0u;
    uint32_t x1 = idx + 42u;
    const uint32_t ks1 = 42u;
    const uint32_t ks2 = 0x1BD11BDAu ^ 42u;

#define TF_R4(a,b,c,d)                                          \
    x0 += x1; x1 = __funnelshift_l(x1, x1, (a)); x1 ^= x0;      \
    x0 += x1; x1 = __funnelshift_l(x1, x1, (b)); x1 ^= x0;      \
    x0 += x1; x1 = __funnelshift_l(x1, x1, (c)); x1 ^= x0;      \
    x0 += x1; x1 = __funnelshift_l(x1, x1, (d)); x1 ^= x0;

    TF_R4(13,15,26, 6)  x0 += ks1;  x1 += ks2 + 1u;
    TF_R4(17,29,16,24)  x0 += ks2;  x1 += 2u;
    TF_R4(13,15,26, 6)              x1 += ks1 + 3u;
    TF_R4(17,29,16,24)  x0 += ks1;  x1 += ks2 + 4u;
    TF_R4(13,15,26, 6)  x0 += ks2;  x1 += 5u;
#undef TF_R4
    return x0 ^ x1;
}

// ---------------------------------------------------------------------------
// Flash attention fp32, FFMA2-packed. CTA = (b, 128 q rows); K tile = 64.
// v == k: swizzled K tile doubles as V. Thread (ty 0..15, tx 0..15):
//   S stage : q rows ty*8..+7, k cols {tx, tx+16, tx+32, tx+48}; 8x4 microtile,
//             accumulators packed along d (even/odd partial sums, hadd at end).
//   PV stage: q rows ty*8..+7, d cols tx*8..+7; 8x8 microtile packed along d.
// k_s float4 slots XOR-swizzled by (row&7); q_s by ((row>>1)&7).
// Dropout RNG gated: entries with s-m <= -18.42 (p < 1e-8) skip threefry.
// ---------------------------------------------------------------------------
__global__ void __launch_bounds__(NT, 1)
attn_kernel(const float* __restrict__ x1, const float* __restrict__ x2,
            float* __restrict__ out)
{
    extern __shared__ float sm[];
    float4* q_s4 = (float4*)sm;                 // [QT][32] swizzled
    float4* k_s4 = (float4*)(sm + QT*DIM);      // [KT][32] swizzled
    float*  p_s  = sm + QT*DIM + KT*DIM;        // [QT][PS]

    const int b   = blockIdx.y;
    const int qt0 = blockIdx.x * QT;
    const int tid = threadIdx.x;
    const int ty  = tid >> 4;
    const int tx  = tid & 15;
    const int r0  = ty << 3;

    const float* Qg = x1 + (size_t)(b*SEQ + qt0) * DIM;
    const float* Kg = x2 + (size_t)b * SEQ * DIM;

    // Q tile -> smem with row-pair swizzle
    for (int idx = tid; idx < QT*DIM/4; idx += NT) {
        const int r = idx >> 5, d4 = idx & 31;
        q_s4[(r << 5) | (d4 ^ ((r >> 1) & 7))] = ((const float4*)Qg)[idx];
    }

    u64 o2[8][4];
    float m[8], l[8];
#pragma unroll
    for (int i = 0; i < 8; ++i) {
        m[i] = -1e30f; l[i] = 0.f;
#pragma unroll
        for (int j = 0; j < 4; ++j) o2[i][j] = 0ull;
    }

    const float SCALE = 3.36358566f;   // 128 ** 0.25

    for (int kt0 = 0; kt0 < SEQ; kt0 += KT) {
        __syncthreads();   // prior PV done before k_s / p_s overwrite
#pragma unroll
        for (int idx = tid; idx < KT*DIM/4; idx += NT) {
            const int c = idx >> 5, d4 = idx & 31;
            k_s4[(c << 5) | (d4 ^ (c & 7))] =
                ((const float4*)(Kg + (size_t)(kt0 + c) * DIM))[d4];
        }
        __syncthreads();

        // ---- S = Q K^T, d-packed FFMA2 ----
        u64 s2[8][4];
#pragma unroll
        for (int i = 0; i < 8; ++i)
#pragma unroll
            for (int j = 0; j < 4; ++j) s2[i][j] = 0ull;

#pragma unroll 4
        for (int d4 = 0; d4 < 32; ++d4) {
            ulonglong2 qv[8], kv[4];
#pragma unroll
            for (int i = 0; i < 8; ++i) {
                const int r = r0 + i;
                qv[i] = *(const ulonglong2*)&q_s4[(r << 5) | (d4 ^ ((r >> 1) & 7))];
            }
#pragma unroll
            for (int jj = 0; jj < 4; ++jj) {
                const int c = tx + (jj << 4);
                kv[jj] = *(const ulonglong2*)&k_s4[(c << 5) | (d4 ^ (c & 7))];
            }
#pragma unroll
            for (int i = 0; i < 8; ++i)
#pragma unroll
                for (int jj = 0; jj < 4; ++jj) {
                    FMA2(s2[i][jj], qv[i].x, kv[jj].x);
                    FMA2(s2[i][jj], qv[i].y, kv[jj].y);
                }
        }

        // ---- online softmax + gated threefry dropout ----
#pragma unroll
        for (int i = 0; i < 8; ++i) {
            float s[4];
#pragma unroll
            for (int jj = 0; jj < 4; ++jj) s[jj] = hadd2(s2[i][jj]) * SCALE;

            float rm = fmaxf(fmaxf(s[0], s[1]), fmaxf(s[2], s[3]));
#pragma unroll
            for (int off = 8; off; off >>= 1)
                rm = fmaxf(rm, __shfl_xor_sync(0xffffffffu, rm, off));

            const float mnew = fmaxf(m[i], rm);
            const float corr = __expf(m[i] - mnew);
            m[i] = mnew;
            const u64 c2 = pack2(corr);
#pragma unroll
            for (int j = 0; j < 4; ++j) MUL2IP(o2[i][j], c2);

            const uint32_t base = (uint32_t)(b*SEQ + qt0 + r0 + i) * (uint32_t)SEQ
                                + (uint32_t)(kt0 + tx);
            float rsum = 0.f;
#pragma unroll
            for (int jj = 0; jj < 4; ++jj) {
                const float dlt = s[jj] - mnew;
                const float e = __expf(dlt);
                rsum += e;
                float val = e;
                if (dlt > -18.42f) {   // p >= ~1e-8: mask matters
                    const uint32_t bits = threefry_bits(base + (jj << 4));
                    const float u = __uint_as_float((bits >> 9) | 0x3f800000u) - 1.0f;
                    val = (u < 0.9f) ? e : 0.f;
                }
                p_s[(r0 + i)*PS + tx + (jj << 4)] = val;
            }
#pragma unroll
            for (int off = 8; off; off >>= 1)
                rsum += __shfl_xor_sync(0xffffffffu, rsum, off);
            l[i] = l[i]*corr + rsum;
        }
        __syncthreads();

        // ---- O += P~ V, d-packed FFMA2 (V = swizzled k_s) ----
#pragma unroll 2
        for (int k0 = 0; k0 < KT; k0 += 4) {
            float4 pv[8];
#pragma unroll
            for (int i = 0; i < 8; ++i)
                pv[i] = *(const float4*)&p_s[(r0 + i)*PS + k0];
#pragma unroll
            for (int u = 0; u < 4; ++u) {
                const int k = k0 + u, sw = k & 7;
                const ulonglong2 va =
                    *(const ulonglong2*)&k_s4[(k << 5) | (((tx << 1)    ) ^ sw)];
                const ulonglong2 vb =
                    *(const ulonglong2*)&k_s4[(k << 5) | (((tx << 1) | 1) ^ sw)];
#pragma unroll
                for (int i = 0; i < 8; ++i) {
                    const float pe = (u == 0) ? pv[i].x : (u == 1) ? pv[i].y
                                   : (u == 2) ? pv[i].z : pv[i].w;
                    const u64 pd = pack2(pe);
                    FMA2(o2[i][0], pd, va.x);
                    FMA2(o2[i][1], pd, va.y);
                    FMA2(o2[i][2], pd, vb.x);
                    FMA2(o2[i][3], pd, vb.y);
                }
            }
        }
    }

    // ---- epilogue ----
#pragma unroll
    for (int i = 0; i < 8; ++i) {
        const float inv = 1.0f / (l[i] * 0.9f);
        float* op = out + (size_t)(b*SEQ + qt0 + r0 + i)*DIM + (tx << 3);
        float v0, v1, v2, v3, v4, v5, v6, v7;
        unpack2(o2[i][0], v0, v1);
        unpack2(o2[i][1], v2, v3);
        unpack2(o2[i][2], v4, v5);
        unpack2(o2[i][3], v6, v7);
        float4 a, c;
        a.x = v0*inv; a.y = v1*inv; a.z = v2*inv; a.w = v3*inv;
        c.x = v4*inv; c.y = v5*inv; c.z = v6*inv; c.w = v7*inv;
        ((float4*)op)[0] = a;
        ((float4*)op)[1] = c;
    }
}

extern "C" void kernel_launch(void* const* d_in, const int* in_sizes, int n_in,
                              void* d_out, int out_size)
{
    (void)in_sizes; (void)n_in; (void)out_size;
    const float* x1 = (const float*)d_in[0];
    const float* x2 = (const float*)d_in[1];
    float* out = (float*)d_out;

    cudaFuncSetAttribute(attn_kernel,
                         cudaFuncAttributeMaxDynamicSharedMemorySize, SMEM_BYTES);

    dim3 grid(SEQ / QT, BATCH);
    attn_kernel<<<grid, NT, SMEM_BYTES>>>(x1, x2, out);
}

// round 3
// speedup vs baseline: 2.2670x; 2.0813x over previous
#include <cuda_runtime.h>
#include <cuda_fp16.h>
#include <cstdint>
#include <cstddef>

#define BATCH 32
#define SEQ   2048
#define DIM   128
#define QT    64
#define KT    64
#define NT    128

// rows padded to 136 fp16 (68 u32): bank-conflict-free fragment loads
#define RP32  68
#define RP16  136

static constexpr int SMEM_BYTES = 4 * 64 * RP32 * 4;  // qh,ql,kh,kl = 69632 B

#define MMA(C, A0, A1, A2, A3, B0, B1)                                  \
    asm volatile("mma.sync.aligned.m16n8k16.row.col.f32.f16.f16.f32 "   \
        "{%0,%1,%2,%3}, {%4,%5,%6,%7}, {%8,%9}, {%0,%1,%2,%3};"         \
        : "+f"(C[0]), "+f"(C[1]), "+f"(C[2]), "+f"(C[3])                \
        : "r"(A0), "r"(A1), "r"(A2), "r"(A3), "r"(B0), "r"(B1))

// split (a,b) fp32 -> packed fp16 hi pair + lo pair (x = hi + lo, ~2^-22 rel)
__device__ __forceinline__ void split2(float a, float b, uint32_t& hi, uint32_t& lo)
{
    __half ha = __float2half_rn(a), hb = __float2half_rn(b);
    __half la = __float2half_rn(a - __half2float(ha));
    __half lb = __float2half_rn(b - __half2float(hb));
    __half2 H = __halves2half2(ha, hb);   // a -> low half
    __half2 L = __halves2half2(la, lb);
    hi = *(uint32_t*)&H;
    lo = *(uint32_t*)&L;
}

__device__ __forceinline__ uint32_t pack16(uint32_t lo, uint32_t hi)
{
    return lo | (hi << 16);
}

// ---------------------------------------------------------------------------
// JAX threefry-2x32 (partitionable fold), key=(0,42). Verified R1/R2.
// ---------------------------------------------------------------------------
__device__ __forceinline__ uint32_t threefry_bits(uint32_t idx)
{
    uint32_t x0 = 0u;
    uint32_t x1 = idx + 42u;
    const uint32_t ks1 = 42u;
    const uint32_t ks2 = 0x1BD11BDAu ^ 42u;

#define TF_R4(a,b,c,d)                                          \
    x0 += x1; x1 = __funnelshift_l(x1, x1, (a)); x1 ^= x0;      \
    x0 += x1; x1 = __funnelshift_l(x1, x1, (b)); x1 ^= x0;      \
    x0 += x1; x1 = __funnelshift_l(x1, x1, (c)); x1 ^= x0;      \
    x0 += x1; x1 = __funnelshift_l(x1, x1, (d)); x1 ^= x0;

    TF_R4(13,15,26, 6)  x0 += ks1;  x1 += ks2 + 1u;
    TF_R4(17,29,16,24)  x0 += ks2;  x1 += 2u;
    TF_R4(13,15,26, 6)              x1 += ks1 + 3u;
    TF_R4(17,29,16,24)  x0 += ks1;  x1 += ks2 + 4u;
    TF_R4(13,15,26, 6)  x0 += ks2;  x1 += 5u;
#undef TF_R4
    return x0 ^ x1;
}

// ---------------------------------------------------------------------------
// fp16x3 flash attention on mma.sync.m16n8k16.
// CTA: 4 warps, QT=64 (warp w -> q rows 16w..16w+15), KT=64 streamed.
// K tile split fp32->(kh,kl) fp16 in smem; doubles as V (v==k):
//   QK^T B-frags: u32 pair loads (pairs along d) from kh/kl
//   PV   B-frags: u16 gathers (pairs along kseq) from the same arrays
// P~ stays in registers (MMA C-layout == A-layout), split hi/lo for PV.
// ---------------------------------------------------------------------------
__global__ void __launch_bounds__(NT, 3)
attn_kernel(const float* __restrict__ x1, const float* __restrict__ x2,
            float* __restrict__ out)
{
    extern __shared__ uint32_t sm32[];
    uint32_t* qh32 = sm32;                 // [64][RP32]
    uint32_t* ql32 = qh32 + 64*RP32;
    uint32_t* kh32 = ql32 + 64*RP32;
    uint32_t* kl32 = kh32 + 64*RP32;
    const unsigned short* kh16 = (const unsigned short*)kh32;   // [64][RP16]
    const unsigned short* kl16 = (const unsigned short*)kl32;

    const int b    = blockIdx.y;
    const int qt0  = blockIdx.x * QT;
    const int tid  = threadIdx.x;
    const int w    = tid >> 5;
    const int lane = tid & 31;
    const int g    = lane >> 2;   // group 0..7
    const int p    = lane & 3;    // 0..3

    const float4* Qg4 = (const float4*)(x1 + (size_t)(b*SEQ + qt0) * DIM);
    const float4* Kg4 = (const float4*)(x2 + (size_t)b * SEQ * DIM);

    const float SCALE = 3.36358566f;   // 128**0.25 folded into Q

    // ---- Q tile -> smem (hi/lo fp16), scaled ----
    for (int i = tid; i < QT*DIM/4; i += NT) {
        const int r = i >> 5, d4 = i & 31;
        float4 v = Qg4[i];
        v.x *= SCALE; v.y *= SCALE; v.z *= SCALE; v.w *= SCALE;
        uint32_t h01, l01, h23, l23;
        split2(v.x, v.y, h01, l01);
        split2(v.z, v.w, h23, l23);
        qh32[r*RP32 + 2*d4    ] = h01;
        qh32[r*RP32 + 2*d4 + 1] = h23;
        ql32[r*RP32 + 2*d4    ] = l01;
        ql32[r*RP32 + 2*d4 + 1] = l23;
    }

    float o[16][4];
    float m0 = -1e30f, m1 = -1e30f, l0 = 0.f, l1 = 0.f;
#pragma unroll
    for (int nt = 0; nt < 16; ++nt)
#pragma unroll
        for (int j = 0; j < 4; ++j) o[nt][j] = 0.f;

    const int rowA0 = (w*16 + g) * RP32;      // A-frag row offsets
    const int rowA1 = rowA0 + 8*RP32;

    for (int kt0 = 0; kt0 < SEQ; kt0 += KT) {
        __syncthreads();   // prior tile's reads of kh/kl done
        // ---- K tile fp32 -> (kh, kl) fp16 smem ----
        for (int i = tid; i < KT*DIM/4; i += NT) {
            const int r = i >> 5, d4 = i & 31;
            float4 v = Kg4[(size_t)(kt0 + r) * 32 + d4];
            uint32_t h01, l01, h23, l23;
            split2(v.x, v.y, h01, l01);
            split2(v.z, v.w, h23, l23);
            kh32[r*RP32 + 2*d4    ] = h01;
            kh32[r*RP32 + 2*d4 + 1] = h23;
            kl32[r*RP32 + 2*d4    ] = l01;
            kl32[r*RP32 + 2*d4 + 1] = l23;
        }
        __syncthreads();

        // ---- S = Q K^T : 3-product fp16 MMA, fp32 accum ----
        float s[8][4];
#pragma unroll
        for (int nt = 0; nt < 8; ++nt)
#pragma unroll
            for (int j = 0; j < 4; ++j) s[nt][j] = 0.f;

#pragma unroll
        for (int kc = 0; kc < 8; ++kc) {
            const int ca = kc*8 + p;
            const uint32_t qa0 = qh32[rowA0 + ca],     qa1 = qh32[rowA1 + ca];
            const uint32_t qa2 = qh32[rowA0 + ca + 4], qa3 = qh32[rowA1 + ca + 4];
            const uint32_t la0 = ql32[rowA0 + ca],     la1 = ql32[rowA1 + ca];
            const uint32_t la2 = ql32[rowA0 + ca + 4], la3 = ql32[rowA1 + ca + 4];
#pragma unroll
            for (int nt = 0; nt < 8; ++nt) {
                const int ib = (nt*8 + g)*RP32 + ca;
                const uint32_t kb0 = kh32[ib], kb1 = kh32[ib + 4];
                const uint32_t lb0 = kl32[ib], lb1 = kl32[ib + 4];
                MMA(s[nt], qa0, qa1, qa2, qa3, kb0, kb1);   // qh*kh
                MMA(s[nt], la0, la1, la2, la3, kb0, kb1);   // ql*kh
                MMA(s[nt], qa0, qa1, qa2, qa3, lb0, lb1);   // qh*kl
            }
        }

        // ---- online softmax + gated threefry dropout ----
        float mx0 = -1e30f, mx1 = -1e30f;
#pragma unroll
        for (int nt = 0; nt < 8; ++nt) {
            mx0 = fmaxf(mx0, fmaxf(s[nt][0], s[nt][1]));
            mx1 = fmaxf(mx1, fmaxf(s[nt][2], s[nt][3]));
        }
        mx0 = fmaxf(mx0, __shfl_xor_sync(0xffffffffu, mx0, 1));
        mx0 = fmaxf(mx0, __shfl_xor_sync(0xffffffffu, mx0, 2));
        mx1 = fmaxf(mx1, __shfl_xor_sync(0xffffffffu, mx1, 1));
        mx1 = fmaxf(mx1, __shfl_xor_sync(0xffffffffu, mx1, 2));

        const float mn0 = fmaxf(m0, mx0), mn1 = fmaxf(m1, mx1);
        const float c0 = __expf(m0 - mn0), c1 = __expf(m1 - mn1);
        m0 = mn0; m1 = mn1;
        l0 *= c0;  l1 *= c1;
#pragma unroll
        for (int nt = 0; nt < 16; ++nt) {
            o[nt][0] *= c0; o[nt][1] *= c0;
            o[nt][2] *= c1; o[nt][3] *= c1;
        }

        const uint32_t rb0 = (uint32_t)(b*SEQ + qt0 + w*16 + g) * (uint32_t)SEQ
                           + (uint32_t)(kt0 + 2*p);
        const uint32_t rb1 = rb0 + 8u * (uint32_t)SEQ;

        uint32_t ph[8][2], pl[8][2];
#pragma unroll
        for (int nt = 0; nt < 8; ++nt) {
            float pm[4];
#pragma unroll
            for (int j = 0; j < 4; ++j) {
                const bool hi8 = (j >= 2);
                const float dlt = s[nt][j] - (hi8 ? mn1 : mn0);
                const float e = __expf(dlt);
                if (hi8) l1 += e; else l0 += e;
                float v = e;
                if (dlt > -18.42f) {   // p >= ~1e-8: mask matters
                    const uint32_t idx = (hi8 ? rb1 : rb0) + nt*8 + (j & 1);
                    const uint32_t bits = threefry_bits(idx);
                    const float u = __uint_as_float((bits >> 9) | 0x3f800000u) - 1.0f;
                    v = (u < 0.9f) ? e : 0.f;
                }
                pm[j] = v;
            }
            split2(pm[0], pm[1], ph[nt][0], pl[nt][0]);
            split2(pm[2], pm[3], ph[nt][1], pl[nt][1]);
        }

        // ---- O += P~ V : 3-product (Ph*Vh + Pl*Vh + Ph*Vl), V == K tile ----
#pragma unroll
        for (int kc2 = 0; kc2 < 4; ++kc2) {
            const uint32_t pa0 = ph[2*kc2][0],   pa1 = ph[2*kc2][1];
            const uint32_t pa2 = ph[2*kc2+1][0], pa3 = ph[2*kc2+1][1];
            const uint32_t qa0 = pl[2*kc2][0],   qa1 = pl[2*kc2][1];
            const uint32_t qa2 = pl[2*kc2+1][0], qa3 = pl[2*kc2+1][1];
            const int k0 = kc2*16 + 2*p;
#pragma unroll
            for (int nt = 0; nt < 16; ++nt) {
                const int d0 = nt*8 + g;
                const int e0 = k0*RP16 + d0;
                const uint32_t b0 = pack16(kh16[e0],           kh16[e0 + RP16]);
                const uint32_t b1 = pack16(kh16[e0 + 8*RP16],  kh16[e0 + 9*RP16]);
                const uint32_t w0 = pack16(kl16[e0],           kl16[e0 + RP16]);
                const uint32_t w1 = pack16(kl16[e0 + 8*RP16],  kl16[e0 + 9*RP16]);
                MMA(o[nt], pa0, pa1, pa2, pa3, b0, b1);   // Ph*Vh
                MMA(o[nt], qa0, qa1, qa2, qa3, b0, b1);   // Pl*Vh
                MMA(o[nt], pa0, pa1, pa2, pa3, w0, w1);   // Ph*Vl
            }
        }
    }

    // ---- epilogue: reduce l across the 4 row-sharing lanes, normalize ----
    l0 += __shfl_xor_sync(0xffffffffu, l0, 1);
    l0 += __shfl_xor_sync(0xffffffffu, l0, 2);
    l1 += __shfl_xor_sync(0xffffffffu, l1, 1);
    l1 += __shfl_xor_sync(0xffffffffu, l1, 2);
    const float inv0 = 1.0f / (l0 * 0.9f);
    const float inv1 = 1.0f / (l1 * 0.9f);

    const int row0 = qt0 + w*16 + g;
    float2* op0 = (float2*)(out + (size_t)(b*SEQ + row0) * DIM);
    float2* op1 = (float2*)(out + (size_t)(b*SEQ + row0 + 8) * DIM);
#pragma unroll
    for (int nt = 0; nt < 16; ++nt) {
        float2 v0, v1;
        v0.x = o[nt][0] * inv0; v0.y = o[nt][1] * inv0;
        v1.x = o[nt][2] * inv1; v1.y = o[nt][3] * inv1;
        op0[nt*4 + p] = v0;
        op1[nt*4 + p] = v1;
    }
}

extern "C" void kernel_launch(void* const* d_in, const int* in_sizes, int n_in,
                              void* d_out, int out_size)
{
    (void)in_sizes; (void)n_in; (void)out_size;
    const float* x1 = (const float*)d_in[0];
    const float* x2 = (const float*)d_in[1];
    float* out = (float*)d_out;

    cudaFuncSetAttribute(attn_kernel,
                         cudaFuncAttributeMaxDynamicSharedMemorySize, SMEM_BYTES);

    dim3 grid(SEQ / QT, BATCH);
    attn_kernel<<<grid, NT, SMEM_BYTES>>>(x1, x2, out);
}

// round 4
// speedup vs baseline: 2.7519x; 1.2139x over previous
#include <cuda_runtime.h>
#include <cuda_fp16.h>
#include <cstdint>
#include <cstddef>

#define BATCH 32
#define SEQ   2048
#define DIM   128
#define QT    64
#define KT    64
#define NT    128

// smem byte offsets: Q hi/lo (16KB each), K 2-stage hi/lo (16KB each)
#define QH_OFF 0
#define QL_OFF 16384
#define KH_OFF(s) (32768 + (s)*32768)
#define KL_OFF(s) (49152 + (s)*32768)
static constexpr int SMEM_BYTES = 98304;

// pre-split fp16 hi/lo copies (u32 = packed half2), [b][seq][d]
#define NPAIR (BATCH*SEQ*DIM/2)
__device__ uint32_t qh_g[NPAIR];
__device__ uint32_t ql_g[NPAIR];
__device__ uint32_t kh_g[NPAIR];
__device__ uint32_t kl_g[NPAIR];

#define MMA(C, A0, A1, A2, A3, B0, B1)                                  \
    asm volatile("mma.sync.aligned.m16n8k16.row.col.f32.f16.f16.f32 "   \
        "{%0,%1,%2,%3}, {%4,%5,%6,%7}, {%8,%9}, {%0,%1,%2,%3};"         \
        : "+f"(C[0]), "+f"(C[1]), "+f"(C[2]), "+f"(C[3])                \
        : "r"(A0), "r"(A1), "r"(A2), "r"(A3), "r"(B0), "r"(B1))

__device__ __forceinline__ void ldsm4(uint32_t& a, uint32_t& b, uint32_t& c,
                                      uint32_t& d, uint32_t addr)
{
    asm volatile("ldmatrix.sync.aligned.m8n8.x4.shared.b16 {%0,%1,%2,%3},[%4];"
                 : "=r"(a), "=r"(b), "=r"(c), "=r"(d) : "r"(addr));
}
__device__ __forceinline__ void ldsm4t(uint32_t& a, uint32_t& b, uint32_t& c,
                                       uint32_t& d, uint32_t addr)
{
    asm volatile("ldmatrix.sync.aligned.m8n8.x4.trans.shared.b16 {%0,%1,%2,%3},[%4];"
                 : "=r"(a), "=r"(b), "=r"(c), "=r"(d) : "r"(addr));
}
__device__ __forceinline__ void cp16(uint32_t dst, const void* src)
{
    asm volatile("cp.async.cg.shared.global [%0], [%1], 16;" :: "r"(dst), "l"(src));
}
#define CP_COMMIT()  asm volatile("cp.async.commit_group;")
#define CP_WAIT1()   asm volatile("cp.async.wait_group 1;")

// split (a,b) fp32 -> packed fp16 hi pair + lo pair (x = hi + lo)
__device__ __forceinline__ void split2(float a, float b, uint32_t& hi, uint32_t& lo)
{
    __half ha = __float2half_rn(a), hb = __float2half_rn(b);
    __half la = __float2half_rn(a - __half2float(ha));
    __half lb = __float2half_rn(b - __half2float(hb));
    __half2 H = __halves2half2(ha, hb);
    __half2 L = __halves2half2(la, lb);
    hi = *(uint32_t*)&H;
    lo = *(uint32_t*)&L;
}

// ---------------------------------------------------------------------------
// JAX threefry-2x32 (partitionable fold), key=(0,42). Verified R1-R3.
// ---------------------------------------------------------------------------
__device__ __forceinline__ uint32_t threefry_bits(uint32_t idx)
{
    uint32_t x0 = 0u;
    uint32_t x1 = idx + 42u;
    const uint32_t ks1 = 42u;
    const uint32_t ks2 = 0x1BD11BDAu ^ 42u;

#define TF_R4(a,b,c,d)                                          \
    x0 += x1; x1 = __funnelshift_l(x1, x1, (a)); x1 ^= x0;      \
    x0 += x1; x1 = __funnelshift_l(x1, x1, (b)); x1 ^= x0;      \
    x0 += x1; x1 = __funnelshift_l(x1, x1, (c)); x1 ^= x0;      \
    x0 += x1; x1 = __funnelshift_l(x1, x1, (d)); x1 ^= x0;

    TF_R4(13,15,26, 6)  x0 += ks1;  x1 += ks2 + 1u;
    TF_R4(17,29,16,24)  x0 += ks2;  x1 += 2u;
    TF_R4(13,15,26, 6)              x1 += ks1 + 3u;
    TF_R4(17,29,16,24)  x0 += ks1;  x1 += ks2 + 4u;
    TF_R4(13,15,26, 6)  x0 += ks2;  x1 += 5u;
#undef TF_R4
    return x0 ^ x1;
}

// ---------------------------------------------------------------------------
// Prepass: split x1 (scaled) and x2 into fp16 hi/lo global arrays.
// ---------------------------------------------------------------------------
__global__ void split_kernel(const float2* __restrict__ x1,
                             const float2* __restrict__ x2)
{
    const float SCALE = 3.36358566f;   // 128**0.25 folded into Q
    int i = blockIdx.x * blockDim.x + threadIdx.x;
    float2 q = x1[i];
    float2 k = x2[i];
    uint32_t h, l;
    split2(q.x * SCALE, q.y * SCALE, h, l);
    qh_g[i] = h; ql_g[i] = l;
    split2(k.x, k.y, h, l);
    kh_g[i] = h; kl_g[i] = l;
}

// smem tile layout: 64 rows x 256B (128 fp16), 16B chunks XOR-swizzled by row&7
__device__ __forceinline__ void load_tile(uint32_t dstH, uint32_t dstL,
                                          const char* srcH, const char* srcL,
                                          int tid)
{
#pragma unroll
    for (int j = 0; j < 8; ++j) {
        const int c   = tid + j * NT;        // 0..1023 16B chunks
        const int row = c >> 4, ch = c & 15;
        const uint32_t off = row * 256 + ((ch ^ (row & 7)) << 4);
        cp16(dstH + off, srcH + c * 16);
        cp16(dstL + off, srcL + c * 16);
    }
}

// ---------------------------------------------------------------------------
// fp16x3 flash attention, ldmatrix + cp.async double-buffered.
// CTA: 4 warps, QT=64 (warp w -> q rows 16w..16w+15), KT=64.
// ---------------------------------------------------------------------------
__global__ void __launch_bounds__(NT, 2)
attn_kernel(float* __restrict__ out)
{
    extern __shared__ char smc[];
    const uint32_t smem = (uint32_t)__cvta_generic_to_shared(smc);

    const int b    = blockIdx.y;
    const int qt0  = blockIdx.x * QT;
    const int tid  = threadIdx.x;
    const int w    = tid >> 5;
    const int lane = tid & 31;
    const int g    = lane >> 2;
    const int p    = lane & 3;
    const int lane7 = lane & 7;
    const int sub   = lane >> 3;

    // ldmatrix addressing (row&7 == lane7 for all types):
    const int rA = lane7 + ((sub & 1) << 3);   // A-frag / trans-B row add
    const int cA = sub >> 1;                   // chunk add
    const int rB = lane7 + ((sub >> 1) << 3);  // B-frag (QK) row add
    const int cB = sub & 1;

    const char* qhb = (const char*)qh_g + (size_t)(b*SEQ + qt0) * 256;
    const char* qlb = (const char*)ql_g + (size_t)(b*SEQ + qt0) * 256;
    const char* khb = (const char*)kh_g + (size_t)b * SEQ * 256;
    const char* klb = (const char*)kl_g + (size_t)b * SEQ * 256;

    // prologue: Q + K tile 0 (group 0), K tile 1 (group 1)
    load_tile(smem + QH_OFF, smem + QL_OFF, qhb, qlb, tid);
    load_tile(smem + KH_OFF(0), smem + KL_OFF(0), khb, klb, tid);
    CP_COMMIT();
    load_tile(smem + KH_OFF(1), smem + KL_OFF(1), khb + KT*256, klb + KT*256, tid);
    CP_COMMIT();

    float o[16][4];
    float m0 = -1e30f, m1 = -1e30f, l0 = 0.f, l1 = 0.f;
#pragma unroll
    for (int nt = 0; nt < 16; ++nt)
#pragma unroll
        for (int j = 0; j < 4; ++j) o[nt][j] = 0.f;

    const uint32_t qrow = smem + QH_OFF + (w*16 + rA) * 256;

    for (int t = 0; t < SEQ/KT; ++t) {
        CP_WAIT1();
        __syncthreads();
        const uint32_t kh0 = smem + KH_OFF(t & 1);

        // ---- S = Q K^T : 3-product fp16 MMA ----
        float s[8][4];
#pragma unroll
        for (int nt = 0; nt < 8; ++nt)
#pragma unroll
            for (int j = 0; j < 4; ++j) s[nt][j] = 0.f;

#pragma unroll
        for (int kc = 0; kc < 8; ++kc) {
            const uint32_t aoff = ((2*kc + cA) ^ lane7) << 4;
            uint32_t qa0, qa1, qa2, qa3, la0, la1, la2, la3;
            ldsm4(qa0, qa1, qa2, qa3, qrow + aoff);
            ldsm4(la0, la1, la2, la3, qrow + aoff + (QL_OFF - QH_OFF));

            const uint32_t boff = ((2*kc + cB) ^ lane7) << 4;
#pragma unroll
            for (int n0g = 0; n0g < 4; ++n0g) {
                const uint32_t baddr = kh0 + (n0g*16 + rB) * 256 + boff;
                uint32_t kb0, kb1, kb2, kb3, lb0, lb1, lb2, lb3;
                ldsm4(kb0, kb1, kb2, kb3, baddr);
                ldsm4(lb0, lb1, lb2, lb3, baddr + 16384);
                const int nt = n0g * 2;
                MMA(s[nt],   qa0, qa1, qa2, qa3, kb0, kb1);
                MMA(s[nt],   la0, la1, la2, la3, kb0, kb1);
                MMA(s[nt],   qa0, qa1, qa2, qa3, lb0, lb1);
                MMA(s[nt+1], qa0, qa1, qa2, qa3, kb2, kb3);
                MMA(s[nt+1], la0, la1, la2, la3, kb2, kb3);
                MMA(s[nt+1], qa0, qa1, qa2, qa3, lb2, lb3);
            }
        }

        // ---- online softmax + gated threefry dropout ----
        float mx0 = -1e30f, mx1 = -1e30f;
#pragma unroll
        for (int nt = 0; nt < 8; ++nt) {
            mx0 = fmaxf(mx0, fmaxf(s[nt][0], s[nt][1]));
            mx1 = fmaxf(mx1, fmaxf(s[nt][2], s[nt][3]));
        }
        mx0 = fmaxf(mx0, __shfl_xor_sync(0xffffffffu, mx0, 1));
        mx0 = fmaxf(mx0, __shfl_xor_sync(0xffffffffu, mx0, 2));
        mx1 = fmaxf(mx1, __shfl_xor_sync(0xffffffffu, mx1, 1));
        mx1 = fmaxf(mx1, __shfl_xor_sync(0xffffffffu, mx1, 2));

        const float mn0 = fmaxf(m0, mx0), mn1 = fmaxf(m1, mx1);
        const float c0 = __expf(m0 - mn0), c1 = __expf(m1 - mn1);
        m0 = mn0; m1 = mn1;
        l0 *= c0;  l1 *= c1;
#pragma unroll
        for (int nt = 0; nt < 16; ++nt) {
            o[nt][0] *= c0; o[nt][1] *= c0;
            o[nt][2] *= c1; o[nt][3] *= c1;
        }

        const uint32_t rb0 = (uint32_t)(b*SEQ + qt0 + w*16 + g) * (uint32_t)SEQ
                           + (uint32_t)(t*KT + 2*p);
        const uint32_t rb1 = rb0 + 8u * (uint32_t)SEQ;

        uint32_t ph[8][2], pl[8][2];
#pragma unroll
        for (int nt = 0; nt < 8; ++nt) {
            float pm[4];
#pragma unroll
            for (int j = 0; j < 4; ++j) {
                const bool hi8 = (j >= 2);
                const float dlt = s[nt][j] - (hi8 ? mn1 : mn0);
                const float e = __expf(dlt);
                if (hi8) l1 += e; else l0 += e;
                float v = e;
                if (dlt > -18.42f) {   // p >= ~1e-8: mask matters
                    const uint32_t idx = (hi8 ? rb1 : rb0) + nt*8 + (j & 1);
                    const uint32_t bits = threefry_bits(idx);
                    const float u = __uint_as_float((bits >> 9) | 0x3f800000u) - 1.0f;
                    v = (u < 0.9f) ? e : 0.f;
                }
                pm[j] = v;
            }
            split2(pm[0], pm[1], ph[nt][0], pl[nt][0]);
            split2(pm[2], pm[3], ph[nt][1], pl[nt][1]);
        }

        // ---- O += P~ V : 3-product, V == K tile via ldmatrix.trans ----
#pragma unroll
        for (int kc2 = 0; kc2 < 4; ++kc2) {
            const uint32_t pa0 = ph[2*kc2][0],   pa1 = ph[2*kc2][1];
            const uint32_t pa2 = ph[2*kc2+1][0], pa3 = ph[2*kc2+1][1];
            const uint32_t qa0 = pl[2*kc2][0],   qa1 = pl[2*kc2][1];
            const uint32_t qa2 = pl[2*kc2+1][0], qa3 = pl[2*kc2+1][1];
            const uint32_t trow = kh0 + (kc2*16 + rA) * 256;
#pragma unroll
            for (int dcp = 0; dcp < 8; ++dcp) {
                const uint32_t toff = ((2*dcp + cA) ^ lane7) << 4;
                uint32_t vb0, vb1, vb2, vb3, wb0, wb1, wb2, wb3;
                ldsm4t(vb0, vb1, vb2, vb3, trow + toff);
                ldsm4t(wb0, wb1, wb2, wb3, trow + toff + 16384);
                const int nt = dcp * 2;
                MMA(o[nt],   pa0, pa1, pa2, pa3, vb0, vb1);
                MMA(o[nt],   qa0, qa1, qa2, qa3, vb0, vb1);
                MMA(o[nt],   pa0, pa1, pa2, pa3, wb0, wb1);
                MMA(o[nt+1], pa0, pa1, pa2, pa3, vb2, vb3);
                MMA(o[nt+1], qa0, qa1, qa2, qa3, vb2, vb3);
                MMA(o[nt+1], pa0, pa1, pa2, pa3, wb2, wb3);
            }
        }

        __syncthreads();
        if (t + 2 < SEQ/KT)
            load_tile(smem + KH_OFF(t & 1), smem + KL_OFF(t & 1),
                      khb + (size_t)(t + 2) * KT * 256,
                      klb + (size_t)(t + 2) * KT * 256, tid);
        CP_COMMIT();   // empty groups near the tail keep wait_group semantics
    }

    // ---- epilogue ----
    l0 += __shfl_xor_sync(0xffffffffu, l0, 1);
    l0 += __shfl_xor_sync(0xffffffffu, l0, 2);
    l1 += __shfl_xor_sync(0xffffffffu, l1, 1);
    l1 += __shfl_xor_sync(0xffffffffu, l1, 2);
    const float inv0 = 1.0f / (l0 * 0.9f);
    const float inv1 = 1.0f / (l1 * 0.9f);

    const int row0 = qt0 + w*16 + g;
    float2* op0 = (float2*)(out + (size_t)(b*SEQ + row0) * DIM);
    float2* op1 = (float2*)(out + (size_t)(b*SEQ + row0 + 8) * DIM);
#pragma unroll
    for (int nt = 0; nt < 16; ++nt) {
        float2 v0, v1;
        v0.x = o[nt][0] * inv0; v0.y = o[nt][1] * inv0;
        v1.x = o[nt][2] * inv1; v1.y = o[nt][3] * inv1;
        op0[nt*4 + p] = v0;
        op1[nt*4 + p] = v1;
    }
}

extern "C" void kernel_launch(void* const* d_in, const int* in_sizes, int n_in,
                              void* d_out, int out_size)
{
    (void)in_sizes; (void)n_in; (void)out_size;
    const float2* x1 = (const float2*)d_in[0];
    const float2* x2 = (const float2*)d_in[1];
    float* out = (float*)d_out;

    split_kernel<<<NPAIR / 256, 256>>>(x1, x2);

    cudaFuncSetAttribute(attn_kernel,
                         cudaFuncAttributeMaxDynamicSharedMemorySize, SMEM_BYTES);
    dim3 grid(SEQ / QT, BATCH);
    attn_kernel<<<grid, NT, SMEM_BYTES>>>(out);
}

// round 5
// speedup vs baseline: 3.0193x; 1.0972x over previous
#include <cuda_runtime.h>
#include <cuda_fp16.h>
#include <cstdint>
#include <cstddef>

#define BATCH 32
#define SEQ   2048
#define DIM   128
#define QT    128
#define KT    64
#define NT    256

// smem byte offsets: Q hi/lo (32KB each), K 2-stage hi/lo (16KB each)
#define QH_OFF 0
#define QL_OFF 32768
#define KH_OFF(s) (65536 + (s)*32768)
#define KL_OFF(s) (81920 + (s)*32768)
static constexpr int SMEM_BYTES = 131072;

// pre-split fp16 hi/lo copies (u32 = packed half2), [b][seq][d]
#define NPAIR (BATCH*SEQ*DIM/2)
__device__ uint32_t qh_g[NPAIR];
__device__ uint32_t ql_g[NPAIR];
__device__ uint32_t kh_g[NPAIR];
__device__ uint32_t kl_g[NPAIR];

#define MMA(C, A0, A1, A2, A3, B0, B1)                                  \
    asm volatile("mma.sync.aligned.m16n8k16.row.col.f32.f16.f16.f32 "   \
        "{%0,%1,%2,%3}, {%4,%5,%6,%7}, {%8,%9}, {%0,%1,%2,%3};"         \
        : "+f"(C[0]), "+f"(C[1]), "+f"(C[2]), "+f"(C[3])                \
        : "r"(A0), "r"(A1), "r"(A2), "r"(A3), "r"(B0), "r"(B1))

__device__ __forceinline__ void ldsm4(uint32_t& a, uint32_t& b, uint32_t& c,
                                      uint32_t& d, uint32_t addr)
{
    asm volatile("ldmatrix.sync.aligned.m8n8.x4.shared.b16 {%0,%1,%2,%3},[%4];"
                 : "=r"(a), "=r"(b), "=r"(c), "=r"(d) : "r"(addr));
}
__device__ __forceinline__ void ldsm4t(uint32_t& a, uint32_t& b, uint32_t& c,
                                       uint32_t& d, uint32_t addr)
{
    asm volatile("ldmatrix.sync.aligned.m8n8.x4.trans.shared.b16 {%0,%1,%2,%3},[%4];"
                 : "=r"(a), "=r"(b), "=r"(c), "=r"(d) : "r"(addr));
}
__device__ __forceinline__ void cp16(uint32_t dst, const void* src)
{
    asm volatile("cp.async.cg.shared.global [%0], [%1], 16;" :: "r"(dst), "l"(src));
}
#define CP_COMMIT()  asm volatile("cp.async.commit_group;")
#define CP_WAIT1()   asm volatile("cp.async.wait_group 1;")

// split (a,b) fp32 -> packed fp16 hi pair + lo pair (x = hi + lo)
__device__ __forceinline__ void split2(float a, float b, uint32_t& hi, uint32_t& lo)
{
    __half ha = __float2half_rn(a), hb = __float2half_rn(b);
    __half la = __float2half_rn(a - __half2float(ha));
    __half lb = __float2half_rn(b - __half2float(hb));
    __half2 H = __halves2half2(ha, hb);
    __half2 L = __halves2half2(la, lb);
    hi = *(uint32_t*)&H;
    lo = *(uint32_t*)&L;
}

// ---------------------------------------------------------------------------
// JAX threefry-2x32 (partitionable fold), key=(0,42). Verified R1-R4.
// ---------------------------------------------------------------------------
__device__ __forceinline__ uint32_t threefry_bits(uint32_t idx)
{
    uint32_t x0 = 0u;
    uint32_t x1 = idx + 42u;
    const uint32_t ks1 = 42u;
    const uint32_t ks2 = 0x1BD11BDAu ^ 42u;

#define TF_R4(a,b,c,d)                                          \
    x0 += x1; x1 = __funnelshift_l(x1, x1, (a)); x1 ^= x0;      \
    x0 += x1; x1 = __funnelshift_l(x1, x1, (b)); x1 ^= x0;      \
    x0 += x1; x1 = __funnelshift_l(x1, x1, (c)); x1 ^= x0;      \
    x0 += x1; x1 = __funnelshift_l(x1, x1, (d)); x1 ^= x0;

    TF_R4(13,15,26, 6)  x0 += ks1;  x1 += ks2 + 1u;
    TF_R4(17,29,16,24)  x0 += ks2;  x1 += 2u;
    TF_R4(13,15,26, 6)              x1 += ks1 + 3u;
    TF_R4(17,29,16,24)  x0 += ks1;  x1 += ks2 + 4u;
    TF_R4(13,15,26, 6)  x0 += ks2;  x1 += 5u;
#undef TF_R4
    return x0 ^ x1;
}

// ---------------------------------------------------------------------------
// Prepass: split x1 (scaled) and x2 into fp16 hi/lo global arrays.
// ---------------------------------------------------------------------------
__global__ void split_kernel(const float2* __restrict__ x1,
                             const float2* __restrict__ x2)
{
    const float SCALE = 3.36358566f;   // 128**0.25 folded into Q
    int i = blockIdx.x * blockDim.x + threadIdx.x;
    float2 q = x1[i];
    float2 k = x2[i];
    uint32_t h, l;
    split2(q.x * SCALE, q.y * SCALE, h, l);
    qh_g[i] = h; ql_g[i] = l;
    split2(k.x, k.y, h, l);
    kh_g[i] = h; kl_g[i] = l;
}

// smem tile: rows x 256B (128 fp16), 16B chunks XOR-swizzled by row&7
template <int CHUNKS>
__device__ __forceinline__ void load_tile(uint32_t dstH, uint32_t dstL,
                                          const char* srcH, const char* srcL,
                                          int tid)
{
#pragma unroll
    for (int j = 0; j < CHUNKS / NT; ++j) {
        const int c   = tid + j * NT;
        const int row = c >> 4, ch = c & 15;
        const uint32_t off = row * 256 + ((ch ^ (row & 7)) << 4);
        cp16(dstH + off, srcH + c * 16);
        cp16(dstL + off, srcL + c * 16);
    }
}

// ---------------------------------------------------------------------------
// fp16 split flash attention, ldmatrix + cp.async double-buffered.
// CTA: 8 warps, QT=128 (warp w -> q rows 16w..16w+15), KT=64.
// QK^T: 3 products (qh*kh + ql*kh + qh*kl). PV: 2 products (ph*vh + pl*vh);
// the dropped ph*vl term is a ~2^-12 (2.4e-4) relative output error.
// ---------------------------------------------------------------------------
__global__ void __launch_bounds__(NT, 1)
attn_kernel(float* __restrict__ out)
{
    extern __shared__ char smc[];
    const uint32_t smem = (uint32_t)__cvta_generic_to_shared(smc);

    const int b    = blockIdx.y;
    const int qt0  = blockIdx.x * QT;
    const int tid  = threadIdx.x;
    const int w    = tid >> 5;
    const int lane = tid & 31;
    const int g    = lane >> 2;
    const int p    = lane & 3;
    const int lane7 = lane & 7;
    const int sub   = lane >> 3;

    // ldmatrix addressing (row&7 == lane7 for all types):
    const int rA = lane7 + ((sub & 1) << 3);   // A-frag / trans-B row add
    const int cA = sub >> 1;                   // chunk add
    const int rB = lane7 + ((sub >> 1) << 3);  // B-frag (QK) row add
    const int cB = sub & 1;

    const char* qhb = (const char*)qh_g + (size_t)(b*SEQ + qt0) * 256;
    const char* qlb = (const char*)ql_g + (size_t)(b*SEQ + qt0) * 256;
    const char* khb = (const char*)kh_g + (size_t)b * SEQ * 256;
    const char* klb = (const char*)kl_g + (size_t)b * SEQ * 256;

    // prologue: Q + K tile 0 (group 0), K tile 1 (group 1)
    load_tile<QT*16>(smem + QH_OFF, smem + QL_OFF, qhb, qlb, tid);
    load_tile<KT*16>(smem + KH_OFF(0), smem + KL_OFF(0), khb, klb, tid);
    CP_COMMIT();
    load_tile<KT*16>(smem + KH_OFF(1), smem + KL_OFF(1), khb + KT*256, klb + KT*256, tid);
    CP_COMMIT();

    float o[16][4];
    float m0 = -1e30f, m1 = -1e30f, l0 = 0.f, l1 = 0.f;
#pragma unroll
    for (int nt = 0; nt < 16; ++nt)
#pragma unroll
        for (int j = 0; j < 4; ++j) o[nt][j] = 0.f;

    const uint32_t qrow = smem + QH_OFF + (w*16 + rA) * 256;

    for (int t = 0; t < SEQ/KT; ++t) {
        CP_WAIT1();
        __syncthreads();
        const uint32_t kh0 = smem + KH_OFF(t & 1);

        // ---- S = Q K^T : 3-product fp16 MMA ----
        float s[8][4];
#pragma unroll
        for (int nt = 0; nt < 8; ++nt)
#pragma unroll
            for (int j = 0; j < 4; ++j) s[nt][j] = 0.f;

#pragma unroll
        for (int kc = 0; kc < 8; ++kc) {
            const uint32_t aoff = ((2*kc + cA) ^ lane7) << 4;
            uint32_t qa0, qa1, qa2, qa3, la0, la1, la2, la3;
            ldsm4(qa0, qa1, qa2, qa3, qrow + aoff);
            ldsm4(la0, la1, la2, la3, qrow + aoff + (QL_OFF - QH_OFF));

            const uint32_t boff = ((2*kc + cB) ^ lane7) << 4;
#pragma unroll
            for (int n0g = 0; n0g < 4; ++n0g) {
                const uint32_t baddr = kh0 + (n0g*16 + rB) * 256 + boff;
                uint32_t kb0, kb1, kb2, kb3, lb0, lb1, lb2, lb3;
                ldsm4(kb0, kb1, kb2, kb3, baddr);
                ldsm4(lb0, lb1, lb2, lb3, baddr + 16384);
                const int nt = n0g * 2;
                MMA(s[nt],   qa0, qa1, qa2, qa3, kb0, kb1);
                MMA(s[nt],   la0, la1, la2, la3, kb0, kb1);
                MMA(s[nt],   qa0, qa1, qa2, qa3, lb0, lb1);
                MMA(s[nt+1], qa0, qa1, qa2, qa3, kb2, kb3);
                MMA(s[nt+1], la0, la1, la2, la3, kb2, kb3);
                MMA(s[nt+1], qa0, qa1, qa2, qa3, lb2, lb3);
            }
        }

        // ---- online softmax + gated threefry dropout ----
        float mx0 = -1e30f, mx1 = -1e30f;
#pragma unroll
        for (int nt = 0; nt < 8; ++nt) {
            mx0 = fmaxf(mx0, fmaxf(s[nt][0], s[nt][1]));
            mx1 = fmaxf(mx1, fmaxf(s[nt][2], s[nt][3]));
        }
        mx0 = fmaxf(mx0, __shfl_xor_sync(0xffffffffu, mx0, 1));
        mx0 = fmaxf(mx0, __shfl_xor_sync(0xffffffffu, mx0, 2));
        mx1 = fmaxf(mx1, __shfl_xor_sync(0xffffffffu, mx1, 1));
        mx1 = fmaxf(mx1, __shfl_xor_sync(0xffffffffu, mx1, 2));

        const float mn0 = fmaxf(m0, mx0), mn1 = fmaxf(m1, mx1);
        const float c0 = __expf(m0 - mn0), c1 = __expf(m1 - mn1);
        m0 = mn0; m1 = mn1;
        l0 *= c0;  l1 *= c1;
#pragma unroll
        for (int nt = 0; nt < 16; ++nt) {
            o[nt][0] *= c0; o[nt][1] *= c0;
            o[nt][2] *= c1; o[nt][3] *= c1;
        }

        const uint32_t rb0 = (uint32_t)(b*SEQ + qt0 + w*16 + g) * (uint32_t)SEQ
                           + (uint32_t)(t*KT + 2*p);
        const uint32_t rb1 = rb0 + 8u * (uint32_t)SEQ;

        uint32_t ph[8][2], pl[8][2];
#pragma unroll
        for (int nt = 0; nt < 8; ++nt) {
            float pm[4];
#pragma unroll
            for (int j = 0; j < 4; ++j) {
                const bool hi8 = (j >= 2);
                const float dlt = s[nt][j] - (hi8 ? mn1 : mn0);
                const float e = __expf(dlt);
                if (hi8) l1 += e; else l0 += e;
                float v = e;
                if (dlt > -18.42f) {   // p >= ~1e-8: mask matters
                    const uint32_t idx = (hi8 ? rb1 : rb0) + nt*8 + (j & 1);
                    const uint32_t bits = threefry_bits(idx);
                    const float u = __uint_as_float((bits >> 9) | 0x3f800000u) - 1.0f;
                    v = (u < 0.9f) ? e : 0.f;
                }
                pm[j] = v;
            }
            split2(pm[0], pm[1], ph[nt][0], pl[nt][0]);
            split2(pm[2], pm[3], ph[nt][1], pl[nt][1]);
        }

        // ---- O += P~ V : 2-product (Ph*Vh + Pl*Vh), V == K tile, trans ----
#pragma unroll
        for (int kc2 = 0; kc2 < 4; ++kc2) {
            const uint32_t pa0 = ph[2*kc2][0],   pa1 = ph[2*kc2][1];
            const uint32_t pa2 = ph[2*kc2+1][0], pa3 = ph[2*kc2+1][1];
            const uint32_t qa0 = pl[2*kc2][0],   qa1 = pl[2*kc2][1];
            const uint32_t qa2 = pl[2*kc2+1][0], qa3 = pl[2*kc2+1][1];
            const uint32_t trow = kh0 + (kc2*16 + rA) * 256;
#pragma unroll
            for (int dcp = 0; dcp < 8; ++dcp) {
                const uint32_t toff = ((2*dcp + cA) ^ lane7) << 4;
                uint32_t vb0, vb1, vb2, vb3;
                ldsm4t(vb0, vb1, vb2, vb3, trow + toff);
                const int nt = dcp * 2;
                MMA(o[nt],   pa0, pa1, pa2, pa3, vb0, vb1);
                MMA(o[nt],   qa0, qa1, qa2, qa3, vb0, vb1);
                MMA(o[nt+1], pa0, pa1, pa2, pa3, vb2, vb3);
                MMA(o[nt+1], qa0, qa1, qa2, qa3, vb2, vb3);
            }
        }

        __syncthreads();
        if (t + 2 < SEQ/KT)
            load_tile<KT*16>(smem + KH_OFF(t & 1), smem + KL_OFF(t & 1),
                             khb + (size_t)(t + 2) * KT * 256,
                             klb + (size_t)(t + 2) * KT * 256, tid);
        CP_COMMIT();   // empty groups near the tail keep wait_group semantics
    }

    // ---- epilogue ----
    l0 += __shfl_xor_sync(0xffffffffu, l0, 1);
    l0 += __shfl_xor_sync(0xffffffffu, l0, 2);
    l1 += __shfl_xor_sync(0xffffffffu, l1, 1);
    l1 += __shfl_xor_sync(0xffffffffu, l1, 2);
    const float inv0 = 1.0f / (l0 * 0.9f);
    const float inv1 = 1.0f / (l1 * 0.9f);

    const int row0 = qt0 + w*16 + g;
    float2* op0 = (float2*)(out + (size_t)(b*SEQ + row0) * DIM);
    float2* op1 = (float2*)(out + (size_t)(b*SEQ + row0 + 8) * DIM);
#pragma unroll
    for (int nt = 0; nt < 16; ++nt) {
        float2 v0, v1;
        v0.x = o[nt][0] * inv0; v0.y = o[nt][1] * inv0;
        v1.x = o[nt][2] * inv1; v1.y = o[nt][3] * inv1;
        op0[nt*4 + p] = v0;
        op1[nt*4 + p] = v1;
    }
}

extern "C" void kernel_launch(void* const* d_in, const int* in_sizes, int n_in,
                              void* d_out, int out_size)
{
    (void)in_sizes; (void)n_in; (void)out_size;
    const float2* x1 = (const float2*)d_in[0];
    const float2* x2 = (const float2*)d_in[1];
    float* out = (float*)d_out;

    split_kernel<<<NPAIR / 256, 256>>>(x1, x2);

    cudaFuncSetAttribute(attn_kernel,
                         cudaFuncAttributeMaxDynamicSharedMemorySize, SMEM_BYTES);
    dim3 grid(SEQ / QT, BATCH);
    attn_kernel<<<grid, NT, SMEM_BYTES>>>(out);
}

// round 6
// speedup vs baseline: 3.9086x; 1.2945x over previous
#include <cuda_runtime.h>
#include <cuda_fp16.h>
#include <cstdint>
#include <cstddef>

#define BATCH 32
#define SEQ   2048
#define DIM   128
#define QT    64
#define KT    32
#define NT    128

// smem: Q hi/lo 16KB each; K stages: (hi 8KB + lo 8KB) x 2
#define QH_OFF 0
#define QL_OFF 16384
#define KH_OFF(s) (32768 + (s)*16384)
#define KL_OFF(s) (40960 + (s)*16384)
static constexpr int SMEM_BYTES = 65536;

// pre-split fp16 hi/lo copies (u32 = packed half2), [b][seq][d]
#define NPAIR (BATCH*SEQ*DIM/2)
__device__ uint32_t qh_g[NPAIR];
__device__ uint32_t ql_g[NPAIR];
__device__ uint32_t kh_g[NPAIR];
__device__ uint32_t kl_g[NPAIR];

#define MMA(C, A0, A1, A2, A3, B0, B1)                                  \
    asm volatile("mma.sync.aligned.m16n8k16.row.col.f32.f16.f16.f32 "   \
        "{%0,%1,%2,%3}, {%4,%5,%6,%7}, {%8,%9}, {%0,%1,%2,%3};"         \
        : "+f"(C[0]), "+f"(C[1]), "+f"(C[2]), "+f"(C[3])                \
        : "r"(A0), "r"(A1), "r"(A2), "r"(A3), "r"(B0), "r"(B1))

__device__ __forceinline__ void ldsm4(uint32_t& a, uint32_t& b, uint32_t& c,
                                      uint32_t& d, uint32_t addr)
{
    asm volatile("ldmatrix.sync.aligned.m8n8.x4.shared.b16 {%0,%1,%2,%3},[%4];"
                 : "=r"(a), "=r"(b), "=r"(c), "=r"(d) : "r"(addr));
}
__device__ __forceinline__ void ldsm4t(uint32_t& a, uint32_t& b, uint32_t& c,
                                       uint32_t& d, uint32_t addr)
{
    asm volatile("ldmatrix.sync.aligned.m8n8.x4.trans.shared.b16 {%0,%1,%2,%3},[%4];"
                 : "=r"(a), "=r"(b), "=r"(c), "=r"(d) : "r"(addr));
}
__device__ __forceinline__ void cp16(uint32_t dst, const void* src)
{
    asm volatile("cp.async.cg.shared.global [%0], [%1], 16;" :: "r"(dst), "l"(src));
}
#define CP_COMMIT()  asm volatile("cp.async.commit_group;")
#define CP_WAIT1()   asm volatile("cp.async.wait_group 1;")

// split (a,b) fp32 -> packed fp16 hi pair + lo pair (x = hi + lo)
__device__ __forceinline__ void split2(float a, float b, uint32_t& hi, uint32_t& lo)
{
    __half ha = __float2half_rn(a), hb = __float2half_rn(b);
    __half la = __float2half_rn(a - __half2float(ha));
    __half lb = __float2half_rn(b - __half2float(hb));
    __half2 H = __halves2half2(ha, hb);
    __half2 L = __halves2half2(la, lb);
    hi = *(uint32_t*)&H;
    lo = *(uint32_t*)&L;
}

// ---------------------------------------------------------------------------
// JAX threefry-2x32 (partitionable fold), key=(0,42). Verified R1-R5.
// ---------------------------------------------------------------------------
__device__ __forceinline__ uint32_t threefry_bits(uint32_t idx)
{
    uint32_t x0 = 0u;
    uint32_t x1 = idx + 42u;
    const uint32_t ks1 = 42u;
    const uint32_t ks2 = 0x1BD11BDAu ^ 42u;

#define TF_R4(a,b,c,d)                                          \
    x0 += x1; x1 = __funnelshift_l(x1, x1, (a)); x1 ^= x0;      \
    x0 += x1; x1 = __funnelshift_l(x1, x1, (b)); x1 ^= x0;      \
    x0 += x1; x1 = __funnelshift_l(x1, x1, (c)); x1 ^= x0;      \
    x0 += x1; x1 = __funnelshift_l(x1, x1, (d)); x1 ^= x0;

    TF_R4(13,15,26, 6)  x0 += ks1;  x1 += ks2 + 1u;
    TF_R4(17,29,16,24)  x0 += ks2;  x1 += 2u;
    TF_R4(13,15,26, 6)              x1 += ks1 + 3u;
    TF_R4(17,29,16,24)  x0 += ks1;  x1 += ks2 + 4u;
    TF_R4(13,15,26, 6)  x0 += ks2;  x1 += 5u;
#undef TF_R4
    return x0 ^ x1;
}

// ---------------------------------------------------------------------------
// Prepass: split x1 (scaled) and x2 into fp16 hi/lo global arrays.
// ---------------------------------------------------------------------------
__global__ void split_kernel(const float2* __restrict__ x1,
                             const float2* __restrict__ x2)
{
    const float SCALE = 3.36358566f;   // 128**0.25 folded into Q
    int i = blockIdx.x * blockDim.x + threadIdx.x;
    float2 q = x1[i];
    float2 k = x2[i];
    uint32_t h, l;
    split2(q.x * SCALE, q.y * SCALE, h, l);
    qh_g[i] = h; ql_g[i] = l;
    split2(k.x, k.y, h, l);
    kh_g[i] = h; kl_g[i] = l;
}

// smem tile: rows x 256B (128 fp16), 16B chunks XOR-swizzled by row&7
template <int CHUNKS>
__device__ __forceinline__ void load_tile(uint32_t dstH, uint32_t dstL,
                                          const char* srcH, const char* srcL,
                                          int tid)
{
#pragma unroll
    for (int j = 0; j < CHUNKS / NT; ++j) {
        const int c   = tid + j * NT;
        const int row = c >> 4, ch = c & 15;
        const uint32_t off = row * 256 + ((ch ^ (row & 7)) << 4);
        cp16(dstH + off, srcH + c * 16);
        cp16(dstL + off, srcL + c * 16);
    }
}

// ---------------------------------------------------------------------------
// fp16 split flash attention. CTA: 4 warps, QT=64, KT=32 (reg-lean: 3 CTAs/SM).
// QK^T: 3 products (qh*kh + ql*kh + qh*kl). PV: 2 products (ph*vh + pl*vh).
// ---------------------------------------------------------------------------
__global__ void __launch_bounds__(NT, 3)
attn_kernel(float* __restrict__ out)
{
    extern __shared__ char smc[];
    const uint32_t smem = (uint32_t)__cvta_generic_to_shared(smc);

    const int b    = blockIdx.y;
    const int qt0  = blockIdx.x * QT;
    const int tid  = threadIdx.x;
    const int w    = tid >> 5;
    const int lane = tid & 31;
    const int g    = lane >> 2;
    const int p    = lane & 3;
    const int lane7 = lane & 7;
    const int sub   = lane >> 3;

    // ldmatrix addressing (row&7 == lane7 for all types):
    const int rA = lane7 + ((sub & 1) << 3);   // A-frag / trans-B row add
    const int cA = sub >> 1;                   // chunk add
    const int rB = lane7 + ((sub >> 1) << 3);  // B-frag (QK) row add
    const int cB = sub & 1;

    const char* qhb = (const char*)qh_g + (size_t)(b*SEQ + qt0) * 256;
    const char* qlb = (const char*)ql_g + (size_t)(b*SEQ + qt0) * 256;
    const char* khb = (const char*)kh_g + (size_t)b * SEQ * 256;
    const char* klb = (const char*)kl_g + (size_t)b * SEQ * 256;

    // prologue: Q + K tile 0 (group 0), K tile 1 (group 1)
    load_tile<QT*16>(smem + QH_OFF, smem + QL_OFF, qhb, qlb, tid);
    load_tile<KT*16>(smem + KH_OFF(0), smem + KL_OFF(0), khb, klb, tid);
    CP_COMMIT();
    load_tile<KT*16>(smem + KH_OFF(1), smem + KL_OFF(1), khb + KT*256, klb + KT*256, tid);
    CP_COMMIT();

    float o[16][4];
    float m0 = -1e30f, m1 = -1e30f, l0 = 0.f, l1 = 0.f;
#pragma unroll
    for (int nt = 0; nt < 16; ++nt)
#pragma unroll
        for (int j = 0; j < 4; ++j) o[nt][j] = 0.f;

    const uint32_t qrow = smem + QH_OFF + (w*16 + rA) * 256;

    for (int t = 0; t < SEQ/KT; ++t) {
        CP_WAIT1();
        __syncthreads();
        const uint32_t kh0 = smem + KH_OFF(t & 1);

        // ---- S = Q K^T : 3-product fp16 MMA (KT=32 -> 4 n-tiles) ----
        float s[4][4];
#pragma unroll
        for (int nt = 0; nt < 4; ++nt)
#pragma unroll
            for (int j = 0; j < 4; ++j) s[nt][j] = 0.f;

#pragma unroll
        for (int kc = 0; kc < 8; ++kc) {
            const uint32_t aoff = ((2*kc + cA) ^ lane7) << 4;
            uint32_t qa0, qa1, qa2, qa3, la0, la1, la2, la3;
            ldsm4(qa0, qa1, qa2, qa3, qrow + aoff);
            ldsm4(la0, la1, la2, la3, qrow + aoff + (QL_OFF - QH_OFF));

            const uint32_t boff = ((2*kc + cB) ^ lane7) << 4;
#pragma unroll
            for (int n0g = 0; n0g < 2; ++n0g) {
                const uint32_t baddr = kh0 + (n0g*16 + rB) * 256 + boff;
                uint32_t kb0, kb1, kb2, kb3, lb0, lb1, lb2, lb3;
                ldsm4(kb0, kb1, kb2, kb3, baddr);
                ldsm4(lb0, lb1, lb2, lb3, baddr + 8192);
                const int nt = n0g * 2;
                // interleaved: adjacent MMAs hit different accumulators
                MMA(s[nt],   qa0, qa1, qa2, qa3, kb0, kb1);
                MMA(s[nt+1], qa0, qa1, qa2, qa3, kb2, kb3);
                MMA(s[nt],   la0, la1, la2, la3, kb0, kb1);
                MMA(s[nt+1], la0, la1, la2, la3, kb2, kb3);
                MMA(s[nt],   qa0, qa1, qa2, qa3, lb0, lb1);
                MMA(s[nt+1], qa0, qa1, qa2, qa3, lb2, lb3);
            }
        }

        // ---- online softmax + gated threefry dropout ----
        float mx0 = -1e30f, mx1 = -1e30f;
#pragma unroll
        for (int nt = 0; nt < 4; ++nt) {
            mx0 = fmaxf(mx0, fmaxf(s[nt][0], s[nt][1]));
            mx1 = fmaxf(mx1, fmaxf(s[nt][2], s[nt][3]));
        }
        mx0 = fmaxf(mx0, __shfl_xor_sync(0xffffffffu, mx0, 1));
        mx0 = fmaxf(mx0, __shfl_xor_sync(0xffffffffu, mx0, 2));
        mx1 = fmaxf(mx1, __shfl_xor_sync(0xffffffffu, mx1, 1));
        mx1 = fmaxf(mx1, __shfl_xor_sync(0xffffffffu, mx1, 2));

        const float mn0 = fmaxf(m0, mx0), mn1 = fmaxf(m1, mx1);
        const float c0 = __expf(m0 - mn0), c1 = __expf(m1 - mn1);
        m0 = mn0; m1 = mn1;
        l0 *= c0;  l1 *= c1;
#pragma unroll
        for (int nt = 0; nt < 16; ++nt) {
            o[nt][0] *= c0; o[nt][1] *= c0;
            o[nt][2] *= c1; o[nt][3] *= c1;
        }

        const uint32_t rb0 = (uint32_t)(b*SEQ + qt0 + w*16 + g) * (uint32_t)SEQ
                           + (uint32_t)(t*KT + 2*p);
        const uint32_t rb1 = rb0 + 8u * (uint32_t)SEQ;

        uint32_t ph[4][2], pl[4][2];
#pragma unroll
        for (int nt = 0; nt < 4; ++nt) {
            float pm[4];
#pragma unroll
            for (int j = 0; j < 4; ++j) {
                const bool hi8 = (j >= 2);
                const float dlt = s[nt][j] - (hi8 ? mn1 : mn0);
                const float e = __expf(dlt);
                if (hi8) l1 += e; else l0 += e;
                float v = e;
                if (dlt > -18.42f) {   // p >= ~1e-8: mask matters
                    const uint32_t idx = (hi8 ? rb1 : rb0) + nt*8 + (j & 1);
                    const uint32_t bits = threefry_bits(idx);
                    const float u = __uint_as_float((bits >> 9) | 0x3f800000u) - 1.0f;
                    v = (u < 0.9f) ? e : 0.f;
                }
                pm[j] = v;
            }
            split2(pm[0], pm[1], ph[nt][0], pl[nt][0]);
            split2(pm[2], pm[3], ph[nt][1], pl[nt][1]);
        }

        // ---- O += P~ V : 2-product (Ph*Vh + Pl*Vh), V == K tile, trans ----
#pragma unroll
        for (int kc2 = 0; kc2 < 2; ++kc2) {
            const uint32_t pa0 = ph[2*kc2][0],   pa1 = ph[2*kc2][1];
            const uint32_t pa2 = ph[2*kc2+1][0], pa3 = ph[2*kc2+1][1];
            const uint32_t qa0 = pl[2*kc2][0],   qa1 = pl[2*kc2][1];
            const uint32_t qa2 = pl[2*kc2+1][0], qa3 = pl[2*kc2+1][1];
            const uint32_t trow = kh0 + (kc2*16 + rA) * 256;
#pragma unroll
            for (int dcp = 0; dcp < 8; ++dcp) {
                const uint32_t toff = ((2*dcp + cA) ^ lane7) << 4;
                uint32_t vb0, vb1, vb2, vb3;
                ldsm4t(vb0, vb1, vb2, vb3, trow + toff);
                const int nt = dcp * 2;
                MMA(o[nt],   pa0, pa1, pa2, pa3, vb0, vb1);
                MMA(o[nt+1], pa0, pa1, pa2, pa3, vb2, vb3);
                MMA(o[nt],   qa0, qa1, qa2, qa3, vb0, vb1);
                MMA(o[nt+1], qa0, qa1, qa2, qa3, vb2, vb3);
            }
        }

        __syncthreads();
        if (t + 2 < SEQ/KT)
            load_tile<KT*16>(smem + KH_OFF(t & 1), smem + KL_OFF(t & 1),
                             khb + (size_t)(t + 2) * KT * 256,
                             klb + (size_t)(t + 2) * KT * 256, tid);
        CP_COMMIT();   // empty groups near the tail keep wait_group semantics
    }

    // ---- epilogue ----
    l0 += __shfl_xor_sync(0xffffffffu, l0, 1);
    l0 += __shfl_xor_sync(0xffffffffu, l0, 2);
    l1 += __shfl_xor_sync(0xffffffffu, l1, 1);
    l1 += __shfl_xor_sync(0xffffffffu, l1, 2);
    const float inv0 = 1.0f / (l0 * 0.9f);
    const float inv1 = 1.0f / (l1 * 0.9f);

    const int row0 = qt0 + w*16 + g;
    float2* op0 = (float2*)(out + (size_t)(b*SEQ + row0) * DIM);
    float2* op1 = (float2*)(out + (size_t)(b*SEQ + row0 + 8) * DIM);
#pragma unroll
    for (int nt = 0; nt < 16; ++nt) {
        float2 v0, v1;
        v0.x = o[nt][0] * inv0; v0.y = o[nt][1] * inv0;
        v1.x = o[nt][2] * inv1; v1.y = o[nt][3] * inv1;
        op0[nt*4 + p] = v0;
        op1[nt*4 + p] = v1;
    }
}

extern "C" void kernel_launch(void* const* d_in, const int* in_sizes, int n_in,
                              void* d_out, int out_size)
{
    (void)in_sizes; (void)n_in; (void)out_size;
    const float2* x1 = (const float2*)d_in[0];
    const float2* x2 = (const float2*)d_in[1];
    float* out = (float*)d_out;

    split_kernel<<<NPAIR / 256, 256>>>(x1, x2);

    cudaFuncSetAttribute(attn_kernel,
                         cudaFuncAttributeMaxDynamicSharedMemorySize, SMEM_BYTES);
    dim3 grid(SEQ / QT, BATCH);
    attn_kernel<<<grid, NT, SMEM_BYTES>>>(out);
}

// round 8
// speedup vs baseline: 4.2999x; 1.1001x over previous
#include <cuda_runtime.h>
#include <cuda_fp16.h>
#include <cstdint>
#include <cstddef>

#define BATCH 32
#define SEQ   2048
#define DIM   128
#define QT    64
#define KT    32
#define NT    128
#define HYST  6.0f

// smem: Q hi/lo 16KB each; K stages: (hi 8KB + lo 8KB) x 2
#define QH_OFF 0
#define QL_OFF 16384
#define KH_OFF(s) (32768 + (s)*16384)
#define KL_OFF(s) (40960 + (s)*16384)
static constexpr int SMEM_BYTES = 65536;

// pre-split fp16 hi/lo copies (u32 = packed half2), [b][seq][d]
#define NPAIR (BATCH*SEQ*DIM/2)
__device__ uint32_t qh_g[NPAIR];
__device__ uint32_t ql_g[NPAIR];
__device__ uint32_t kh_g[NPAIR];
__device__ uint32_t kl_g[NPAIR];

#define MMA(C, A0, A1, A2, A3, B0, B1)                                  \
    asm volatile("mma.sync.aligned.m16n8k16.row.col.f32.f16.f16.f32 "   \
        "{%0,%1,%2,%3}, {%4,%5,%6,%7}, {%8,%9}, {%0,%1,%2,%3};"         \
        : "+f"(C[0]), "+f"(C[1]), "+f"(C[2]), "+f"(C[3])                \
        : "r"(A0), "r"(A1), "r"(A2), "r"(A3), "r"(B0), "r"(B1))

__device__ __forceinline__ void ldsm4(uint32_t& a, uint32_t& b, uint32_t& c,
                                      uint32_t& d, uint32_t addr)
{
    asm volatile("ldmatrix.sync.aligned.m8n8.x4.shared.b16 {%0,%1,%2,%3},[%4];"
                 : "=r"(a), "=r"(b), "=r"(c), "=r"(d) : "r"(addr));
}
__device__ __forceinline__ void ldsm4t(uint32_t& a, uint32_t& b, uint32_t& c,
                                       uint32_t& d, uint32_t addr)
{
    asm volatile("ldmatrix.sync.aligned.m8n8.x4.trans.shared.b16 {%0,%1,%2,%3},[%4];"
                 : "=r"(a), "=r"(b), "=r"(c), "=r"(d) : "r"(addr));
}
__device__ __forceinline__ void cp16(uint32_t dst, const void* src)
{
    asm volatile("cp.async.cg.shared.global [%0], [%1], 16;" :: "r"(dst), "l"(src));
}
#define CP_COMMIT()  asm volatile("cp.async.commit_group;")
#define CP_WAIT1()   asm volatile("cp.async.wait_group 1;")

// split (a,b) fp32 -> packed fp16 hi pair + lo pair (x = hi + lo)
__device__ __forceinline__ void split2(float a, float b, uint32_t& hi, uint32_t& lo)
{
    __half ha = __float2half_rn(a), hb = __float2half_rn(b);
    __half la = __float2half_rn(a - __half2float(ha));
    __half lb = __float2half_rn(b - __half2float(hb));
    __half2 H = __halves2half2(ha, hb);
    __half2 L = __halves2half2(la, lb);
    hi = *(uint32_t*)&H;
    lo = *(uint32_t*)&L;
}

// ---------------------------------------------------------------------------
// JAX threefry-2x32 (partitionable fold), key=(0,42). Verified R1-R6.
// ---------------------------------------------------------------------------
__device__ __forceinline__ uint32_t threefry_bits(uint32_t idx)
{
    uint32_t x0 = 0u;
    uint32_t x1 = idx + 42u;
    const uint32_t ks1 = 42u;
    const uint32_t ks2 = 0x1BD11BDAu ^ 42u;

#define TF_R4(a,b,c,d)                                          \
    x0 += x1; x1 = __funnelshift_l(x1, x1, (a)); x1 ^= x0;      \
    x0 += x1; x1 = __funnelshift_l(x1, x1, (b)); x1 ^= x0;      \
    x0 += x1; x1 = __funnelshift_l(x1, x1, (c)); x1 ^= x0;      \
    x0 += x1; x1 = __funnelshift_l(x1, x1, (d)); x1 ^= x0;

    TF_R4(13,15,26, 6)  x0 += ks1;  x1 += ks2 + 1u;
    TF_R4(17,29,16,24)  x0 += ks2;  x1 += 2u;
    TF_R4(13,15,26, 6)              x1 += ks1 + 3u;
    TF_R4(17,29,16,24)  x0 += ks1;  x1 += ks2 + 4u;
    TF_R4(13,15,26, 6)  x0 += ks2;  x1 += 5u;
#undef TF_R4
    return x0 ^ x1;
}

// ---------------------------------------------------------------------------
// Prepass: split x1 (scaled) and x2 into fp16 hi/lo global arrays.
// ---------------------------------------------------------------------------
__global__ void split_kernel(const float2* __restrict__ x1,
                             const float2* __restrict__ x2)
{
    const float SCALE = 3.36358566f;   // 128**0.25 folded into Q
    int i = blockIdx.x * blockDim.x + threadIdx.x;
    float2 q = x1[i];
    float2 k = x2[i];
    uint32_t h, l;
    split2(q.x * SCALE, q.y * SCALE, h, l);
    qh_g[i] = h; ql_g[i] = l;
    split2(k.x, k.y, h, l);
    kh_g[i] = h; kl_g[i] = l;
}

// smem tile: rows x 256B (128 fp16), 16B chunks XOR-swizzled by row&7
template <int CHUNKS>
__device__ __forceinline__ void load_tile(uint32_t dstH, uint32_t dstL,
                                          const char* srcH, const char* srcL,
                                          int tid)
{
#pragma unroll
    for (int j = 0; j < CHUNKS / NT; ++j) {
        const int c   = tid + j * NT;
        const int row = c >> 4, ch = c & 15;
        const uint32_t off = row * 256 + ((ch ^ (row & 7)) << 4);
        cp16(dstH + off, srcH + c * 16);
        cp16(dstL + off, srcL + c * 16);
    }
}

// ---------------------------------------------------------------------------
// fp16 split flash attention. CTA: 4 warps, QT=64, KT=32 (3 CTAs/SM).
// QK^T: 3 products (qh*kh + ql*kh + qh*kl).  PV: 1 product (ph*vh; dropped
// pl*vh and ph*vl terms are each ~2^-12 relative -> ~4e-4 output rel err).
// Softmax: hysteresis running max (rescale only when tile max beats m by
// >HYST; P up to e^HYST fits fp16), exp+RNG gated to near-max entries.
// ---------------------------------------------------------------------------
__global__ void __launch_bounds__(NT, 3)
attn_kernel(float* __restrict__ out)
{
    extern __shared__ char smc[];
    const uint32_t smem = (uint32_t)__cvta_generic_to_shared(smc);

    const int b    = blockIdx.y;
    const int qt0  = blockIdx.x * QT;
    const int tid  = threadIdx.x;
    const int w    = tid >> 5;
    const int lane = tid & 31;
    const int g    = lane >> 2;
    const int p    = lane & 3;
    const int lane7 = lane & 7;
    const int sub   = lane >> 3;

    // ldmatrix addressing (row&7 == lane7 for all types):
    const int rA = lane7 + ((sub & 1) << 3);   // A-frag / trans-B row add
    const int cA = sub >> 1;                   // chunk add
    const int rB = lane7 + ((sub >> 1) << 3);  // B-frag (QK) row add
    const int cB = sub & 1;

    const char* qhb = (const char*)qh_g + (size_t)(b*SEQ + qt0) * 256;
    const char* qlb = (const char*)ql_g + (size_t)(b*SEQ + qt0) * 256;
    const char* khb = (const char*)kh_g + (size_t)b * SEQ * 256;
    const char* klb = (const char*)kl_g + (size_t)b * SEQ * 256;

    // prologue: Q + K tile 0 (group 0), K tile 1 (group 1)
    load_tile<QT*16>(smem + QH_OFF, smem + QL_OFF, qhb, qlb, tid);
    load_tile<KT*16>(smem + KH_OFF(0), smem + KL_OFF(0), khb, klb, tid);
    CP_COMMIT();
    load_tile<KT*16>(smem + KH_OFF(1), smem + KL_OFF(1), khb + KT*256, klb + KT*256, tid);
    CP_COMMIT();

    float o[16][4];
    float m0 = -1e30f, m1 = -1e30f, l0 = 0.f, l1 = 0.f;
#pragma unroll
    for (int nt = 0; nt < 16; ++nt)
#pragma unroll
        for (int j = 0; j < 4; ++j) o[nt][j] = 0.f;

    const uint32_t qrow = smem + QH_OFF + (w*16 + rA) * 256;

    for (int t = 0; t < SEQ/KT; ++t) {
        CP_WAIT1();
        __syncthreads();
        const uint32_t kh0 = smem + KH_OFF(t & 1);

        // ---- S = Q K^T : 3-product fp16 MMA (KT=32 -> 4 n-tiles) ----
        float s[4][4];
#pragma unroll
        for (int nt = 0; nt < 4; ++nt)
#pragma unroll
            for (int j = 0; j < 4; ++j) s[nt][j] = 0.f;

#pragma unroll
        for (int kc = 0; kc < 8; ++kc) {
            const uint32_t aoff = ((2*kc + cA) ^ lane7) << 4;
            uint32_t qa0, qa1, qa2, qa3, la0, la1, la2, la3;
            ldsm4(qa0, qa1, qa2, qa3, qrow + aoff);
            ldsm4(la0, la1, la2, la3, qrow + aoff + (QL_OFF - QH_OFF));

            const uint32_t boff = ((2*kc + cB) ^ lane7) << 4;
#pragma unroll
            for (int n0g = 0; n0g < 2; ++n0g) {
                const uint32_t baddr = kh0 + (n0g*16 + rB) * 256 + boff;
                uint32_t kb0, kb1, kb2, kb3, lb0, lb1, lb2, lb3;
                ldsm4(kb0, kb1, kb2, kb3, baddr);
                ldsm4(lb0, lb1, lb2, lb3, baddr + 8192);
                const int nt = n0g * 2;
                // interleaved: adjacent MMAs hit different accumulators
                MMA(s[nt],   qa0, qa1, qa2, qa3, kb0, kb1);
                MMA(s[nt+1], qa0, qa1, qa2, qa3, kb2, kb3);
                MMA(s[nt],   la0, la1, la2, la3, kb0, kb1);
                MMA(s[nt+1], la0, la1, la2, la3, kb2, kb3);
                MMA(s[nt],   qa0, qa1, qa2, qa3, lb0, lb1);
                MMA(s[nt+1], qa0, qa1, qa2, qa3, lb2, lb3);
            }
        }

        // ---- hysteresis online max ----
        float mx0 = -1e30f, mx1 = -1e30f;
#pragma unroll
        for (int nt = 0; nt < 4; ++nt) {
            mx0 = fmaxf(mx0, fmaxf(s[nt][0], s[nt][1]));
            mx1 = fmaxf(mx1, fmaxf(s[nt][2], s[nt][3]));
        }
        mx0 = fmaxf(mx0, __shfl_xor_sync(0xffffffffu, mx0, 1));
        mx0 = fmaxf(mx0, __shfl_xor_sync(0xffffffffu, mx0, 2));
        mx1 = fmaxf(mx1, __shfl_xor_sync(0xffffffffu, mx1, 1));
        mx1 = fmaxf(mx1, __shfl_xor_sync(0xffffffffu, mx1, 2));

        float c0 = 1.f, c1 = 1.f;
        int flag = 0;
        if (mx0 > m0 + HYST) { c0 = __expf(m0 - mx0); m0 = mx0; l0 *= c0; flag = 1; }
        if (mx1 > m1 + HYST) { c1 = __expf(m1 - mx1); m1 = mx1; l1 *= c1; flag = 1; }

        if (__ballot_sync(0xffffffffu, flag)) {   // rare: rescale O
#pragma unroll
            for (int nt = 0; nt < 16; ++nt) {
                o[nt][0] *= c0; o[nt][1] *= c0;
                o[nt][2] *= c1; o[nt][3] *= c1;
            }
        }

        // ---- gated exp + threefry dropout; pack P hi (fp16) ----
        const uint32_t rb0 = (uint32_t)(b*SEQ + qt0 + w*16 + g) * (uint32_t)SEQ
                           + (uint32_t)(t*KT + 2*p);
        const uint32_t rb1 = rb0 + 8u * (uint32_t)SEQ;

        uint32_t ph[4][2];
#pragma unroll
        for (int nt = 0; nt < 4; ++nt) {
            float pm[4];
#pragma unroll
            for (int j = 0; j < 4; ++j) {
                const bool hi8 = (j >= 2);
                const float dlt = s[nt][j] - (hi8 ? m1 : m0);
                float v = 0.f;
                if (dlt > -18.42f) {   // p/pmax >= ~1e-8: term matters
                    const float e = __expf(dlt);
                    if (hi8) l1 += e; else l0 += e;
                    const uint32_t idx = (hi8 ? rb1 : rb0) + nt*8 + (j & 1);
                    const uint32_t bits = threefry_bits(idx);
                    const float u = __uint_as_float((bits >> 9) | 0x3f800000u) - 1.0f;
                    v = (u < 0.9f) ? e : 0.f;
                }
                pm[j] = v;
            }
            __half2 h01 = __floats2half2_rn(pm[0], pm[1]);
            __half2 h23 = __floats2half2_rn(pm[2], pm[3]);
            ph[nt][0] = *(uint32_t*)&h01;
            ph[nt][1] = *(uint32_t*)&h23;
        }

        // ---- O += P~ V : 1 product (Ph*Vh), V == K tile, trans ----
#pragma unroll
        for (int kc2 = 0; kc2 < 2; ++kc2) {
            const uint32_t pa0 = ph[2*kc2][0],   pa1 = ph[2*kc2][1];
            const uint32_t pa2 = ph[2*kc2+1][0], pa3 = ph[2*kc2+1][1];
            const uint32_t trow = kh0 + (kc2*16 + rA) * 256;
#pragma unroll
            for (int dcp = 0; dcp < 8; ++dcp) {
                const uint32_t toff = ((2*dcp + cA) ^ lane7) << 4;
                uint32_t vb0, vb1, vb2, vb3;
                ldsm4t(vb0, vb1, vb2, vb3, trow + toff);
                const int nt = dcp * 2;
                MMA(o[nt],   pa0, pa1, pa2, pa3, vb0, vb1);
                MMA(o[nt+1], pa0, pa1, pa2, pa3, vb2, vb3);
            }
        }

        __syncthreads();
        if (t + 2 < SEQ/KT)
            load_tile<KT*16>(smem + KH_OFF(t & 1), smem + KL_OFF(t & 1),
                             khb + (size_t)(t + 2) * KT * 256,
                             klb + (size_t)(t + 2) * KT * 256, tid);
        CP_COMMIT();   // empty groups near the tail keep wait_group semantics
    }

    // ---- epilogue ----
    l0 += __shfl_xor_sync(0xffffffffu, l0, 1);
    l0 += __shfl_xor_sync(0xffffffffu, l0, 2);
    l1 += __shfl_xor_sync(0xffffffffu, l1, 1);
    l1 += __shfl_xor_sync(0xffffffffu, l1, 2);
    const float inv0 = 1.0f / (l0 * 0.9f);
    const float inv1 = 1.0f / (l1 * 0.9f);

    const int row0 = qt0 + w*16 + g;
    float2* op0 = (float2*)(out + (size_t)(b*SEQ + row0) * DIM);
    float2* op1 = (float2*)(out + (size_t)(b*SEQ + row0 + 8) * DIM);
#pragma unroll
    for (int nt = 0; nt < 16; ++nt) {
        float2 v0, v1;
        v0.x = o[nt][0] * inv0; v0.y = o[nt][1] * inv0;
        v1.x = o[nt][2] * inv1; v1.y = o[nt][3] * inv1;
        op0[nt*4 + p] = v0;
        op1[nt*4 + p] = v1;
    }
}

extern "C" void kernel_launch(void* const* d_in, const int* in_sizes, int n_in,
                              void* d_out, int out_size)
{
    (void)in_sizes; (void)n_in; (void)out_size;
    const float2* x1 = (const float2*)d_in[0];
    const float2* x2 = (const float2*)d_in[1];
    float* out = (float*)d_out;

    split_kernel<<<NPAIR / 256, 256>>>(x1, x2);

    cudaFuncSetAttribute(attn_kernel,
                         cudaFuncAttributeMaxDynamicSharedMemorySize, SMEM_BYTES);
    dim3 grid(SEQ / QT, BATCH);
    attn_kernel<<<grid, NT, SMEM_BYTES>>>(out);
}